// round 3
// baseline (speedup 1.0000x reference)
#include <cuda_runtime.h>
#include <cuda_bf16.h>

// Problem constants (fixed shapes)
#define NNODES 100000
#define NEDGES 3200000
#define C 128           // feature dim (in = hid = out = 128)

// ---------------- scratch (static device globals; no allocation) ----------------
__device__ int   g_src[NEDGES];
__device__ int   g_dst[NEDGES];
__device__ int   g_csr[NEDGES];
__device__ int   g_cnt[NNODES];
__device__ int   g_off[NNODES];
__device__ int   g_rowptr[NNODES + 1];
__device__ float g_dinv[NNODES];
__device__ __align__(16) float g_h[(size_t)NNODES * C];    // GEMM output (reused both layers)
__device__ __align__(16) float g_buf[(size_t)NNODES * C];  // layer-1 aggregated+relu output

// ---------------- kernels ----------------

__global__ void zero_cnt_off_kernel(int n) {
    int i = blockIdx.x * blockDim.x + threadIdx.x;
    if (i < n) { g_cnt[i] = 0; g_off[i] = 0; }
}

// Edge index is int32 (JAX x64 disabled downgrades int64 -> int32).
// Copy src/dst, histogram dst degree.
__global__ void conv_hist_kernel(const int* __restrict__ ei, int nedges) {
    int e = blockIdx.x * blockDim.x + threadIdx.x;
    if (e >= nedges) return;
    int s = ei[e];
    int d = ei[nedges + e];
    g_src[e] = s;
    g_dst[e] = d;
    atomicAdd(&g_cnt[d], 1);
}

// Single-block exclusive scan of g_cnt -> g_rowptr (shuffle-based).
__global__ void scan_kernel(int n) {
    __shared__ int warp_sums[32];
    __shared__ int s_carry;
    int tid  = threadIdx.x;
    int lane = tid & 31;
    int wid  = tid >> 5;
    if (tid == 0) s_carry = 0;
    __syncthreads();
    for (int base = 0; base < n; base += 1024) {
        int i = base + tid;
        int v = (i < n) ? g_cnt[i] : 0;
        // warp inclusive scan
        int x = v;
        #pragma unroll
        for (int off = 1; off < 32; off <<= 1) {
            int t = __shfl_up_sync(0xffffffffu, x, off);
            if (lane >= off) x += t;
        }
        if (lane == 31) warp_sums[wid] = x;
        __syncthreads();
        if (wid == 0) {
            int ws = warp_sums[lane];
            #pragma unroll
            for (int off = 1; off < 32; off <<= 1) {
                int t = __shfl_up_sync(0xffffffffu, ws, off);
                if (lane >= off) ws += t;
            }
            warp_sums[lane] = ws;  // inclusive warp totals
        }
        __syncthreads();
        int warp_off = (wid == 0) ? 0 : warp_sums[wid - 1];
        int carry = s_carry;
        if (i < n) g_rowptr[i] = carry + warp_off + x - v;  // exclusive
        int tile_total = warp_sums[31];
        __syncthreads();
        if (tid == 0) s_carry = carry + tile_total;
        __syncthreads();
    }
    if (threadIdx.x == 0) g_rowptr[n] = s_carry;
}

// dinv = rsqrt(deg) with deg = in-degree + 1 (self loop) -> always > 0
__global__ void dinv_kernel(int n) {
    int i = blockIdx.x * blockDim.x + threadIdx.x;
    if (i < n) g_dinv[i] = rsqrtf((float)(g_cnt[i] + 1));
}

// Fill CSR (by destination) with source indices.
__global__ void fill_kernel(int nedges) {
    int e = blockIdx.x * blockDim.x + threadIdx.x;
    if (e >= nedges) return;
    int d = g_dst[e];
    int pos = g_rowptr[d] + atomicAdd(&g_off[d], 1);
    g_csr[pos] = g_src[e];
}

// Y = X @ W   (fp32, smem tiled). LAYER=1: X = param x, Y = g_h.
//                                 LAYER=2: X = g_buf,   Y = g_h.
// block: 32x8 threads, 32 rows x 128 cols per block; each thread 4 rows x 4 cols.
template <int LAYER>
__global__ __launch_bounds__(256) void gemm128_kernel(
    const float* __restrict__ Xin, const float* __restrict__ W, int nrows) {
    __shared__ float Ws[64][128];   // 32 KB
    __shared__ float Xs[32][64];    // 8 KB
    const float* __restrict__ X = (LAYER == 1) ? Xin : (const float*)g_buf;
    float* __restrict__ Y = g_h;
    const int tx = threadIdx.x;         // 0..31 -> col group
    const int ty = threadIdx.y;         // 0..7  -> row group
    const int tid = ty * 32 + tx;
    const int row0 = blockIdx.x * 32;

    float acc[4][4] = {};
    for (int kt = 0; kt < 128; kt += 64) {
        // load W tile [kt..kt+64) x 128 : 2048 float4
        const float4* Wg = (const float4*)&W[kt * 128];
        float4* Wsm = (float4*)&Ws[0][0];
        #pragma unroll
        for (int i = tid; i < 2048; i += 256) Wsm[i] = Wg[i];
        // load X tile 32 rows x 64 k : 512 float4
        #pragma unroll
        for (int i = tid; i < 512; i += 256) {
            int r  = i >> 4;        // /16
            int k4 = i & 15;
            int rr = row0 + r;
            if (rr < nrows)
                ((float4*)&Xs[r][0])[k4] = ((const float4*)&X[(size_t)rr * C + kt])[k4];
        }
        __syncthreads();
        #pragma unroll 8
        for (int k = 0; k < 64; k++) {
            float4 w4 = *(const float4*)&Ws[k][tx * 4];
            #pragma unroll
            for (int ri = 0; ri < 4; ri++) {
                float xv = Xs[ty + ri * 8][k];
                acc[ri][0] += xv * w4.x;
                acc[ri][1] += xv * w4.y;
                acc[ri][2] += xv * w4.z;
                acc[ri][3] += xv * w4.w;
            }
        }
        __syncthreads();
    }
    #pragma unroll
    for (int ri = 0; ri < 4; ri++) {
        int r = row0 + ty + ri * 8;
        if (r < nrows) {
            float4 o = make_float4(acc[ri][0], acc[ri][1], acc[ri][2], acc[ri][3]);
            *(float4*)&Y[(size_t)r * C + tx * 4] = o;
        }
    }
}

// warp-per-destination-row SpMM: out[d] = sum_{e in row d} H[src_e]*dinv[s]*dinv[d]
//                                        + H[d]*dinv[d]^2 + bias  (optional relu)
// LAYER=1: reads g_h, writes g_buf (+relu). LAYER=2: reads g_h, writes param out.
template <int LAYER>
__global__ __launch_bounds__(256) void spmm_kernel(
    const float* __restrict__ bias, float* __restrict__ outp, int n) {
    int warp = (blockIdx.x * blockDim.x + threadIdx.x) >> 5;
    int lane = threadIdx.x & 31;
    if (warp >= n) return;
    const float4* __restrict__ H4 = (const float4*)g_h;
    float* __restrict__ out = (LAYER == 1) ? (float*)g_buf : outp;
    float dd = g_dinv[warp];
    // self loop
    float4 a = H4[(size_t)warp * 32 + lane];
    float w0 = dd * dd;
    float4 acc = make_float4(a.x * w0, a.y * w0, a.z * w0, a.w * w0);
    int e0 = g_rowptr[warp];
    int e1 = g_rowptr[warp + 1];
    int e = e0;
    // 4-way unrolled gather for MLP
    for (; e + 4 <= e1; e += 4) {
        int s0 = g_csr[e + 0];
        int s1 = g_csr[e + 1];
        int s2 = g_csr[e + 2];
        int s3 = g_csr[e + 3];
        float wA = g_dinv[s0] * dd;
        float wB = g_dinv[s1] * dd;
        float wC = g_dinv[s2] * dd;
        float wD = g_dinv[s3] * dd;
        float4 h0 = H4[(size_t)s0 * 32 + lane];
        float4 h1 = H4[(size_t)s1 * 32 + lane];
        float4 h2 = H4[(size_t)s2 * 32 + lane];
        float4 h3 = H4[(size_t)s3 * 32 + lane];
        acc.x += h0.x * wA; acc.y += h0.y * wA; acc.z += h0.z * wA; acc.w += h0.w * wA;
        acc.x += h1.x * wB; acc.y += h1.y * wB; acc.z += h1.z * wB; acc.w += h1.w * wB;
        acc.x += h2.x * wC; acc.y += h2.y * wC; acc.z += h2.z * wC; acc.w += h2.w * wC;
        acc.x += h3.x * wD; acc.y += h3.y * wD; acc.z += h3.z * wD; acc.w += h3.w * wD;
    }
    for (; e < e1; e++) {
        int s = g_csr[e];
        float w = g_dinv[s] * dd;
        float4 hv = H4[(size_t)s * 32 + lane];
        acc.x += hv.x * w;
        acc.y += hv.y * w;
        acc.z += hv.z * w;
        acc.w += hv.w * w;
    }
    float4 b = ((const float4*)bias)[lane];
    acc.x += b.x; acc.y += b.y; acc.z += b.z; acc.w += b.w;
    if (LAYER == 1) {
        acc.x = fmaxf(acc.x, 0.f);
        acc.y = fmaxf(acc.y, 0.f);
        acc.z = fmaxf(acc.z, 0.f);
        acc.w = fmaxf(acc.w, 0.f);
    }
    ((float4*)out)[(size_t)warp * 32 + lane] = acc;
}

// ---------------- launch ----------------
extern "C" void kernel_launch(void* const* d_in, const int* in_sizes, int n_in,
                              void* d_out, int out_size) {
    const float* x  = (const float*)d_in[0];
    const int*   ei = (const int*)d_in[1];     // int32 edge index (2 x E)
    const float* W1 = (const float*)d_in[2];
    const float* b1 = (const float*)d_in[3];
    const float* W2 = (const float*)d_in[4];
    const float* b2 = (const float*)d_in[5];
    float* out = (float*)d_out;

    const int nedges = in_sizes[1] / 2;   // 3,200,000
    const int n = NNODES;

    // 1) zero counters
    zero_cnt_off_kernel<<<(n + 255) / 256, 256>>>(n);
    // 2) edge split + degree histogram
    conv_hist_kernel<<<(nedges + 255) / 256, 256>>>(ei, nedges);
    // 3) exclusive scan -> rowptr
    scan_kernel<<<1, 1024>>>(n);
    // 4) dinv
    dinv_kernel<<<(n + 255) / 256, 256>>>(n);
    // 5) fill CSR
    fill_kernel<<<(nedges + 255) / 256, 256>>>(nedges);

    const int gemm_blocks = (n + 31) / 32;        // 3125
    const int spmm_blocks = (n * 32 + 255) / 256; // warp per row

    // Layer 1: g_h = x @ W1 ; g_buf = relu(A_norm g_h + b1)
    gemm128_kernel<1><<<gemm_blocks, dim3(32, 8)>>>(x, W1, n);
    spmm_kernel<1><<<spmm_blocks, 256>>>(b1, nullptr, n);
    // Layer 2: g_h = g_buf @ W2 ; out = A_norm g_h + b2
    gemm128_kernel<2><<<gemm_blocks, dim3(32, 8)>>>(nullptr, W2, n);
    spmm_kernel<2><<<spmm_blocks, 256>>>(b2, out, n);
}

// round 4
// speedup vs baseline: 1.0109x; 1.0109x over previous
#include <cuda_runtime.h>
#include <cuda_bf16.h>

// Problem constants (fixed shapes)
#define NNODES 100000
#define NEDGES 3200000
#define C 128           // feature dim (in = hid = out = 128)

// ---------------- scratch (static device globals; no allocation) ----------------
__device__ int   g_csr[NEDGES];
__device__ int   g_cnt[NNODES];
__device__ int   g_off[NNODES];
__device__ int   g_rowptr[NNODES + 1];
__device__ int   g_bsum[128];
__device__ int   g_boff[128];
__device__ float g_dinv[NNODES];
__device__ __align__(16) float g_h[(size_t)NNODES * C];    // GEMM output (reused both layers)
__device__ __align__(16) float g_buf[(size_t)NNODES * C];  // layer-1 aggregated+relu output

// ---------------- f32x2 helpers ----------------
__device__ __forceinline__ unsigned long long fma2(unsigned long long a,
                                                   unsigned long long b,
                                                   unsigned long long c) {
    unsigned long long d;
    asm("fma.rn.f32x2 %0, %1, %2, %3;" : "=l"(d) : "l"(a), "l"(b), "l"(c));
    return d;
}
__device__ __forceinline__ unsigned long long splat2(float x) {
    unsigned long long r;
    asm("mov.b64 %0, {%1, %1};" : "=l"(r) : "f"(x));
    return r;
}
__device__ __forceinline__ float2 unpack2(unsigned long long v) {
    float2 f;
    asm("mov.b64 {%0, %1}, %2;" : "=f"(f.x), "=f"(f.y) : "l"(v));
    return f;
}

// ---------------- prologue kernels ----------------

__global__ void zero_cnt_off_kernel(int n) {
    int i = blockIdx.x * blockDim.x + threadIdx.x;
    if (i < n) { g_cnt[i] = 0; g_off[i] = 0; }
}

// histogram of dst degree (edge index is int32)
__global__ void hist_kernel(const int* __restrict__ ei, int nedges) {
    int e = blockIdx.x * blockDim.x + threadIdx.x;
    if (e >= nedges) return;
    atomicAdd(&g_cnt[ei[nedges + e]], 1);
}

// phase 1: per-block (1024 elems) exclusive scan into rowptr, block sums to g_bsum
__global__ __launch_bounds__(1024) void scan1_kernel(int n) {
    __shared__ int warp_sums[32];
    int tid = threadIdx.x, lane = tid & 31, wid = tid >> 5;
    int i = blockIdx.x * 1024 + tid;
    int v = (i < n) ? g_cnt[i] : 0;
    int x = v;
    #pragma unroll
    for (int off = 1; off < 32; off <<= 1) {
        int t = __shfl_up_sync(0xffffffffu, x, off);
        if (lane >= off) x += t;
    }
    if (lane == 31) warp_sums[wid] = x;
    __syncthreads();
    if (wid == 0) {
        int ws = warp_sums[lane];
        #pragma unroll
        for (int off = 1; off < 32; off <<= 1) {
            int t = __shfl_up_sync(0xffffffffu, ws, off);
            if (lane >= off) ws += t;
        }
        warp_sums[lane] = ws;
    }
    __syncthreads();
    int woff = wid ? warp_sums[wid - 1] : 0;
    if (i < n) g_rowptr[i] = woff + x - v;       // block-local exclusive
    if (tid == 1023) g_bsum[blockIdx.x] = woff + x;
}

// phase 2: scan 98 block sums (single 128-thread block)
__global__ void scan2_kernel(int nb, int n) {
    __shared__ int ws[4];
    int tid = threadIdx.x, lane = tid & 31, wid = tid >> 5;
    int v = (tid < nb) ? g_bsum[tid] : 0;
    int x = v;
    #pragma unroll
    for (int off = 1; off < 32; off <<= 1) {
        int t = __shfl_up_sync(0xffffffffu, x, off);
        if (lane >= off) x += t;
    }
    if (lane == 31) ws[wid] = x;
    __syncthreads();
    int woff = 0;
    for (int w = 0; w < wid; w++) woff += ws[w];
    int excl = woff + x - v;
    if (tid < nb) g_boff[tid] = excl;
    if (tid == nb - 1) g_rowptr[n] = excl + v;
}

// phase 3: add block offsets + compute dinv (deg = in-deg + 1 self loop)
__global__ void scan3_dinv_kernel(int n) {
    int i = blockIdx.x * blockDim.x + threadIdx.x;
    if (i < n) {
        g_rowptr[i] += g_boff[i >> 10];
        g_dinv[i] = rsqrtf((float)(g_cnt[i] + 1));
    }
}

// fill CSR (by destination) with source indices, reading edge index directly
__global__ void fill_kernel(const int* __restrict__ ei, int nedges) {
    int e = blockIdx.x * blockDim.x + threadIdx.x;
    if (e >= nedges) return;
    int d = ei[nedges + e];
    int pos = g_rowptr[d] + atomicAdd(&g_off[d], 1);
    g_csr[pos] = ei[e];
}

// ---------------- GEMM: Y = X @ W via packed fma.rn.f32x2 ----------------
// Tile 128 rows x 128 cols, KT=32 k-slab. 256 threads = 8 warps.
// lane -> 4 cols (conflict-free LDS.128 on W pairs); warp -> 16 rows.
// X slab stored pre-splatted (u64, value duplicated) so inner loop is
// LDS.64 broadcast + 2x FFMA2 per (row, k). Static smem = 48KB exactly.
template <int LAYER>
__global__ __launch_bounds__(256) void gemm128_kernel(
    const float* __restrict__ Xin, const float* __restrict__ W, int nrows) {
    __shared__ unsigned long long XsS[128][32];  // 32 KB (splatted x)
    __shared__ float Ws[32][128];                // 16 KB
    const float* __restrict__ X = (LAYER == 1) ? Xin : (const float*)g_buf;
    float* __restrict__ Y = g_h;

    const int tid  = threadIdx.x;
    const int lane = tid & 31;
    const int wid  = tid >> 5;
    const int row_blk = blockIdx.x * 128;
    const int row0 = wid * 16;

    unsigned long long acc[16][2];
    #pragma unroll
    for (int r = 0; r < 16; r++) { acc[r][0] = 0ull; acc[r][1] = 0ull; }

    for (int kt = 0; kt < 128; kt += 32) {
        // W slab: rows [kt, kt+32) x 128 cols = 1024 float4
        const float4* Wg = (const float4*)&W[kt * 128];
        float4* Wsm = (float4*)&Ws[0][0];
        #pragma unroll
        for (int i = tid; i < 1024; i += 256) Wsm[i] = Wg[i];
        // X slab: 128 rows x 32 k = 1024 float4, splat-stored
        #pragma unroll
        for (int i = tid; i < 1024; i += 256) {
            int r = i >> 3;         // 8 float4 per row
            int j = i & 7;
            int gr = row_blk + r;
            float4 v = (gr < nrows) ? ((const float4*)&X[(size_t)gr * C + kt])[j]
                                    : make_float4(0.f, 0.f, 0.f, 0.f);
            XsS[r][4 * j + 0] = splat2(v.x);
            XsS[r][4 * j + 1] = splat2(v.y);
            XsS[r][4 * j + 2] = splat2(v.z);
            XsS[r][4 * j + 3] = splat2(v.w);
        }
        __syncthreads();
        #pragma unroll 4
        for (int k = 0; k < 32; k++) {
            ulonglong2 w = *(const ulonglong2*)&Ws[k][lane * 4];
            #pragma unroll
            for (int r = 0; r < 16; r++) {
                unsigned long long xv = XsS[row0 + r][k];
                acc[r][0] = fma2(xv, w.x, acc[r][0]);
                acc[r][1] = fma2(xv, w.y, acc[r][1]);
            }
        }
        __syncthreads();
    }
    #pragma unroll
    for (int r = 0; r < 16; r++) {
        int gr = row_blk + row0 + r;
        if (gr < nrows) {
            float2 a = unpack2(acc[r][0]);
            float2 b = unpack2(acc[r][1]);
            *(float4*)&Y[(size_t)gr * C + lane * 4] = make_float4(a.x, a.y, b.x, b.y);
        }
    }
}

// ---------------- SpMM: warp-per-destination-row ----------------
// out[d] = sum_{e in row d} H[src_e]*dinv[s]*dinv[d] + H[d]*dinv[d]^2 + bias
// LAYER=1: reads g_h, writes g_buf (+relu). LAYER=2: reads g_h, writes param out.
template <int LAYER>
__global__ __launch_bounds__(256) void spmm_kernel(
    const float* __restrict__ bias, float* __restrict__ outp, int n) {
    int warp = (blockIdx.x * blockDim.x + threadIdx.x) >> 5;
    int lane = threadIdx.x & 31;
    if (warp >= n) return;
    const float4* __restrict__ H4 = (const float4*)g_h;
    float* __restrict__ out = (LAYER == 1) ? (float*)g_buf : outp;
    float dd = g_dinv[warp];
    float4 a = H4[(size_t)warp * 32 + lane];
    float w0 = dd * dd;
    float4 acc = make_float4(a.x * w0, a.y * w0, a.z * w0, a.w * w0);
    int e0 = g_rowptr[warp];
    int e1 = g_rowptr[warp + 1];
    int e = e0;
    for (; e + 4 <= e1; e += 4) {
        int s0 = g_csr[e + 0];
        int s1 = g_csr[e + 1];
        int s2 = g_csr[e + 2];
        int s3 = g_csr[e + 3];
        float wA = g_dinv[s0] * dd;
        float wB = g_dinv[s1] * dd;
        float wC = g_dinv[s2] * dd;
        float wD = g_dinv[s3] * dd;
        float4 h0 = H4[(size_t)s0 * 32 + lane];
        float4 h1 = H4[(size_t)s1 * 32 + lane];
        float4 h2 = H4[(size_t)s2 * 32 + lane];
        float4 h3 = H4[(size_t)s3 * 32 + lane];
        acc.x += h0.x * wA; acc.y += h0.y * wA; acc.z += h0.z * wA; acc.w += h0.w * wA;
        acc.x += h1.x * wB; acc.y += h1.y * wB; acc.z += h1.z * wB; acc.w += h1.w * wB;
        acc.x += h2.x * wC; acc.y += h2.y * wC; acc.z += h2.z * wC; acc.w += h2.w * wC;
        acc.x += h3.x * wD; acc.y += h3.y * wD; acc.z += h3.z * wD; acc.w += h3.w * wD;
    }
    for (; e < e1; e++) {
        int s = g_csr[e];
        float w = g_dinv[s] * dd;
        float4 hv = H4[(size_t)s * 32 + lane];
        acc.x += hv.x * w; acc.y += hv.y * w; acc.z += hv.z * w; acc.w += hv.w * w;
    }
    float4 b = ((const float4*)bias)[lane];
    acc.x += b.x; acc.y += b.y; acc.z += b.z; acc.w += b.w;
    if (LAYER == 1) {
        acc.x = fmaxf(acc.x, 0.f);
        acc.y = fmaxf(acc.y, 0.f);
        acc.z = fmaxf(acc.z, 0.f);
        acc.w = fmaxf(acc.w, 0.f);
    }
    ((float4*)out)[(size_t)warp * 32 + lane] = acc;
}

// ---------------- launch ----------------
extern "C" void kernel_launch(void* const* d_in, const int* in_sizes, int n_in,
                              void* d_out, int out_size) {
    const float* x  = (const float*)d_in[0];
    const int*   ei = (const int*)d_in[1];     // int32 edge index (2 x E)
    const float* W1 = (const float*)d_in[2];
    const float* b1 = (const float*)d_in[3];
    const float* W2 = (const float*)d_in[4];
    const float* b2 = (const float*)d_in[5];
    float* out = (float*)d_out;

    const int nedges = in_sizes[1] / 2;   // 3,200,000
    const int n = NNODES;
    const int nb = (n + 1023) / 1024;     // 98 scan blocks

    zero_cnt_off_kernel<<<(n + 255) / 256, 256>>>(n);
    hist_kernel<<<(nedges + 255) / 256, 256>>>(ei, nedges);
    scan1_kernel<<<nb, 1024>>>(n);
    scan2_kernel<<<1, 128>>>(nb, n);
    scan3_dinv_kernel<<<(n + 255) / 256, 256>>>(n);
    fill_kernel<<<(nedges + 255) / 256, 256>>>(ei, nedges);

    const int gemm_blocks = (n + 127) / 128;      // 782
    const int spmm_blocks = (n * 32 + 255) / 256; // warp per row

    gemm128_kernel<1><<<gemm_blocks, 256>>>(x, W1, n);
    spmm_kernel<1><<<spmm_blocks, 256>>>(b1, nullptr, n);
    gemm128_kernel<2><<<gemm_blocks, 256>>>(nullptr, W2, n);
    spmm_kernel<2><<<spmm_blocks, 256>>>(b2, out, n);
}

// round 5
// speedup vs baseline: 1.0648x; 1.0533x over previous
#include <cuda_runtime.h>
#include <cuda_fp16.h>

// Problem constants (fixed shapes)
#define NNODES 100000
#define NEDGES 3200000
#define C 128           // feature dim (in = hid = out = 128)

// ---------------- scratch (static device globals; no allocation) ----------------
__device__ int    g_csr[NEDGES];
__device__ int    g_cnt[NNODES];
__device__ int    g_off[NNODES];
__device__ int    g_rowptr[NNODES + 1];
__device__ int    g_bsum[128];
__device__ int    g_boff[128];
__device__ float  g_dinv[NNODES];
__device__ __align__(16) __half g_h[(size_t)NNODES * C];   // GEMM output, fp16 (gathered)
__device__ __align__(16) float  g_buf[(size_t)NNODES * C]; // layer-1 agg+relu output (fp32)

// ---------------- f32x2 helpers ----------------
__device__ __forceinline__ unsigned long long fma2(unsigned long long a,
                                                   unsigned long long b,
                                                   unsigned long long c) {
    unsigned long long d;
    asm("fma.rn.f32x2 %0, %1, %2, %3;" : "=l"(d) : "l"(a), "l"(b), "l"(c));
    return d;
}
__device__ __forceinline__ unsigned long long splat2(float x) {
    unsigned long long r;
    asm("mov.b64 %0, {%1, %1};" : "=l"(r) : "f"(x));
    return r;
}
__device__ __forceinline__ float2 unpack2(unsigned long long v) {
    float2 f;
    asm("mov.b64 {%0, %1}, %2;" : "=f"(f.x), "=f"(f.y) : "l"(v));
    return f;
}

// ---------------- prologue kernels ----------------

__global__ void zero_cnt_off_kernel(int n) {
    int i = blockIdx.x * blockDim.x + threadIdx.x;
    if (i < n) { g_cnt[i] = 0; g_off[i] = 0; }
}

// histogram of dst degree (edge index is int32)
__global__ void hist_kernel(const int* __restrict__ ei, int nedges) {
    int e = blockIdx.x * blockDim.x + threadIdx.x;
    if (e >= nedges) return;
    atomicAdd(&g_cnt[ei[nedges + e]], 1);
}

// phase 1: per-block (1024 elems) exclusive scan into rowptr, block sums to g_bsum
__global__ __launch_bounds__(1024) void scan1_kernel(int n) {
    __shared__ int warp_sums[32];
    int tid = threadIdx.x, lane = tid & 31, wid = tid >> 5;
    int i = blockIdx.x * 1024 + tid;
    int v = (i < n) ? g_cnt[i] : 0;
    int x = v;
    #pragma unroll
    for (int off = 1; off < 32; off <<= 1) {
        int t = __shfl_up_sync(0xffffffffu, x, off);
        if (lane >= off) x += t;
    }
    if (lane == 31) warp_sums[wid] = x;
    __syncthreads();
    if (wid == 0) {
        int ws = warp_sums[lane];
        #pragma unroll
        for (int off = 1; off < 32; off <<= 1) {
            int t = __shfl_up_sync(0xffffffffu, ws, off);
            if (lane >= off) ws += t;
        }
        warp_sums[lane] = ws;
    }
    __syncthreads();
    int woff = wid ? warp_sums[wid - 1] : 0;
    if (i < n) g_rowptr[i] = woff + x - v;       // block-local exclusive
    if (tid == 1023) g_bsum[blockIdx.x] = woff + x;
}

// phase 2: scan 98 block sums (single 128-thread block)
__global__ void scan2_kernel(int nb, int n) {
    __shared__ int ws[4];
    int tid = threadIdx.x, lane = tid & 31, wid = tid >> 5;
    int v = (tid < nb) ? g_bsum[tid] : 0;
    int x = v;
    #pragma unroll
    for (int off = 1; off < 32; off <<= 1) {
        int t = __shfl_up_sync(0xffffffffu, x, off);
        if (lane >= off) x += t;
    }
    if (lane == 31) ws[wid] = x;
    __syncthreads();
    int woff = 0;
    for (int w = 0; w < wid; w++) woff += ws[w];
    int excl = woff + x - v;
    if (tid < nb) g_boff[tid] = excl;
    if (tid == nb - 1) g_rowptr[n] = excl + v;
}

// phase 3: add block offsets + compute dinv (deg = in-deg + 1 self loop)
__global__ void scan3_dinv_kernel(int n) {
    int i = blockIdx.x * blockDim.x + threadIdx.x;
    if (i < n) {
        g_rowptr[i] += g_boff[i >> 10];
        g_dinv[i] = rsqrtf((float)(g_cnt[i] + 1));
    }
}

// fill CSR (by destination) with source indices, reading edge index directly
__global__ void fill_kernel(const int* __restrict__ ei, int nedges) {
    int e = blockIdx.x * blockDim.x + threadIdx.x;
    if (e >= nedges) return;
    int d = ei[nedges + e];
    int pos = g_rowptr[d] + atomicAdd(&g_off[d], 1);
    g_csr[pos] = ei[e];
}

// ---------------- GEMM: g_h(fp16) = X(fp32) @ W via packed fma.rn.f32x2 ----------------
// Tile 128 rows x 128 cols, KT=32 k-slab. 256 threads = 8 warps.
// lane -> 4 cols; warp -> 16 rows. X slab pre-splatted u64 in smem.
template <int LAYER>
__global__ __launch_bounds__(256) void gemm128_kernel(
    const float* __restrict__ Xin, const float* __restrict__ W, int nrows) {
    __shared__ unsigned long long XsS[128][32];  // 32 KB (splatted x)
    __shared__ float Ws[32][128];                // 16 KB
    const float* __restrict__ X = (LAYER == 1) ? Xin : (const float*)g_buf;

    const int tid  = threadIdx.x;
    const int lane = tid & 31;
    const int wid  = tid >> 5;
    const int row_blk = blockIdx.x * 128;
    const int row0 = wid * 16;

    unsigned long long acc[16][2];
    #pragma unroll
    for (int r = 0; r < 16; r++) { acc[r][0] = 0ull; acc[r][1] = 0ull; }

    for (int kt = 0; kt < 128; kt += 32) {
        const float4* Wg = (const float4*)&W[kt * 128];
        float4* Wsm = (float4*)&Ws[0][0];
        #pragma unroll
        for (int i = tid; i < 1024; i += 256) Wsm[i] = Wg[i];
        #pragma unroll
        for (int i = tid; i < 1024; i += 256) {
            int r = i >> 3;
            int j = i & 7;
            int gr = row_blk + r;
            float4 v = (gr < nrows) ? ((const float4*)&X[(size_t)gr * C + kt])[j]
                                    : make_float4(0.f, 0.f, 0.f, 0.f);
            XsS[r][4 * j + 0] = splat2(v.x);
            XsS[r][4 * j + 1] = splat2(v.y);
            XsS[r][4 * j + 2] = splat2(v.z);
            XsS[r][4 * j + 3] = splat2(v.w);
        }
        __syncthreads();
        #pragma unroll 4
        for (int k = 0; k < 32; k++) {
            ulonglong2 w = *(const ulonglong2*)&Ws[k][lane * 4];
            #pragma unroll
            for (int r = 0; r < 16; r++) {
                unsigned long long xv = XsS[row0 + r][k];
                acc[r][0] = fma2(xv, w.x, acc[r][0]);
                acc[r][1] = fma2(xv, w.y, acc[r][1]);
            }
        }
        __syncthreads();
    }
    #pragma unroll
    for (int r = 0; r < 16; r++) {
        int gr = row_blk + row0 + r;
        if (gr < nrows) {
            float2 a = unpack2(acc[r][0]);
            float2 b = unpack2(acc[r][1]);
            __half2 h01 = __floats2half2_rn(a.x, a.y);
            __half2 h23 = __floats2half2_rn(b.x, b.y);
            uint2 st;
            st.x = *(unsigned int*)&h01;
            st.y = *(unsigned int*)&h23;
            ((uint2*)&g_h[(size_t)gr * C])[lane] = st;
        }
    }
}

// ---------------- SpMM: warp-per-destination-row, fp16 gather, fp32 accumulate ----
// out[d] = sum_{e in row d} H[src_e]*dinv[s]*dinv[d] + H[d]*dinv[d]^2 + bias
// LAYER=1: writes g_buf (+relu, fp32). LAYER=2: writes param out (fp32).
template <int LAYER>
__global__ __launch_bounds__(256) void spmm_kernel(
    const float* __restrict__ bias, float* __restrict__ outp, int n) {
    int warp = (blockIdx.x * blockDim.x + threadIdx.x) >> 5;
    int lane = threadIdx.x & 31;
    if (warp >= n) return;
    const uint2* __restrict__ H2 = (const uint2*)g_h;  // 8B per lane = 4 halves
    float* __restrict__ out = (LAYER == 1) ? (float*)g_buf : outp;
    float dd = g_dinv[warp];

    float4 acc;
    {
        uint2 raw = H2[(size_t)warp * 32 + lane];
        float2 f0 = __half22float2(*(const __half2*)&raw.x);
        float2 f1 = __half22float2(*(const __half2*)&raw.y);
        float w0 = dd * dd;
        acc = make_float4(f0.x * w0, f0.y * w0, f1.x * w0, f1.y * w0);
    }
    int e0 = g_rowptr[warp];
    int e1 = g_rowptr[warp + 1];
    int e = e0;
    for (; e + 4 <= e1; e += 4) {
        int s0 = g_csr[e + 0];
        int s1 = g_csr[e + 1];
        int s2 = g_csr[e + 2];
        int s3 = g_csr[e + 3];
        float wA = g_dinv[s0] * dd;
        float wB = g_dinv[s1] * dd;
        float wC = g_dinv[s2] * dd;
        float wD = g_dinv[s3] * dd;
        uint2 r0 = H2[(size_t)s0 * 32 + lane];
        uint2 r1 = H2[(size_t)s1 * 32 + lane];
        uint2 r2 = H2[(size_t)s2 * 32 + lane];
        uint2 r3 = H2[(size_t)s3 * 32 + lane];
        {
            float2 f0 = __half22float2(*(const __half2*)&r0.x);
            float2 f1 = __half22float2(*(const __half2*)&r0.y);
            acc.x += f0.x * wA; acc.y += f0.y * wA; acc.z += f1.x * wA; acc.w += f1.y * wA;
        }
        {
            float2 f0 = __half22float2(*(const __half2*)&r1.x);
            float2 f1 = __half22float2(*(const __half2*)&r1.y);
            acc.x += f0.x * wB; acc.y += f0.y * wB; acc.z += f1.x * wB; acc.w += f1.y * wB;
        }
        {
            float2 f0 = __half22float2(*(const __half2*)&r2.x);
            float2 f1 = __half22float2(*(const __half2*)&r2.y);
            acc.x += f0.x * wC; acc.y += f0.y * wC; acc.z += f1.x * wC; acc.w += f1.y * wC;
        }
        {
            float2 f0 = __half22float2(*(const __half2*)&r3.x);
            float2 f1 = __half22float2(*(const __half2*)&r3.y);
            acc.x += f0.x * wD; acc.y += f0.y * wD; acc.z += f1.x * wD; acc.w += f1.y * wD;
        }
    }
    for (; e < e1; e++) {
        int s = g_csr[e];
        float w = g_dinv[s] * dd;
        uint2 raw = H2[(size_t)s * 32 + lane];
        float2 f0 = __half22float2(*(const __half2*)&raw.x);
        float2 f1 = __half22float2(*(const __half2*)&raw.y);
        acc.x += f0.x * w; acc.y += f0.y * w; acc.z += f1.x * w; acc.w += f1.y * w;
    }
    float4 b = ((const float4*)bias)[lane];
    acc.x += b.x; acc.y += b.y; acc.z += b.z; acc.w += b.w;
    if (LAYER == 1) {
        acc.x = fmaxf(acc.x, 0.f);
        acc.y = fmaxf(acc.y, 0.f);
        acc.z = fmaxf(acc.z, 0.f);
        acc.w = fmaxf(acc.w, 0.f);
    }
    ((float4*)out)[(size_t)warp * 32 + lane] = acc;
}

// ---------------- launch ----------------
extern "C" void kernel_launch(void* const* d_in, const int* in_sizes, int n_in,
                              void* d_out, int out_size) {
    const float* x  = (const float*)d_in[0];
    const int*   ei = (const int*)d_in[1];     // int32 edge index (2 x E)
    const float* W1 = (const float*)d_in[2];
    const float* b1 = (const float*)d_in[3];
    const float* W2 = (const float*)d_in[4];
    const float* b2 = (const float*)d_in[5];
    float* out = (float*)d_out;

    const int nedges = in_sizes[1] / 2;   // 3,200,000
    const int n = NNODES;
    const int nb = (n + 1023) / 1024;     // 98 scan blocks

    zero_cnt_off_kernel<<<(n + 255) / 256, 256>>>(n);
    hist_kernel<<<(nedges + 255) / 256, 256>>>(ei, nedges);
    scan1_kernel<<<nb, 1024>>>(n);
    scan2_kernel<<<1, 128>>>(nb, n);
    scan3_dinv_kernel<<<(n + 255) / 256, 256>>>(n);
    fill_kernel<<<(nedges + 255) / 256, 256>>>(ei, nedges);

    const int gemm_blocks = (n + 127) / 128;      // 782
    const int spmm_blocks = (n * 32 + 255) / 256; // warp per row

    gemm128_kernel<1><<<gemm_blocks, 256>>>(x, W1, n);
    spmm_kernel<1><<<spmm_blocks, 256>>>(b1, nullptr, n);
    gemm128_kernel<2><<<gemm_blocks, 256>>>(nullptr, W2, n);
    spmm_kernel<2><<<spmm_blocks, 256>>>(b2, out, n);
}

// round 6
// speedup vs baseline: 1.2131x; 1.1393x over previous
#include <cuda_runtime.h>
#include <cuda_fp16.h>

// Problem constants (fixed shapes)
#define NNODES 100000
#define NEDGES 3200000
#define C 128           // feature dim (in = hid = out = 128)

// ---------------- scratch (static device globals; no allocation) ----------------
__device__ int    g_csr[NEDGES];
__device__ int    g_cnt[NNODES];
__device__ int    g_off[NNODES];
__device__ int    g_rowptr[NNODES + 1];
__device__ int    g_bsum[128];
__device__ int    g_boff[128];
__device__ float  g_dinv[NNODES];
__device__ __align__(16) __half g_h[(size_t)NNODES * C];   // dinv-prescaled GEMM out, fp16
__device__ __align__(16) float  g_buf[(size_t)NNODES * C]; // layer-1 agg+relu output (fp32)

// ---------------- f32x2 helpers ----------------
__device__ __forceinline__ unsigned long long fma2(unsigned long long a,
                                                   unsigned long long b,
                                                   unsigned long long c) {
    unsigned long long d;
    asm("fma.rn.f32x2 %0, %1, %2, %3;" : "=l"(d) : "l"(a), "l"(b), "l"(c));
    return d;
}
__device__ __forceinline__ unsigned long long splat2(float x) {
    unsigned long long r;
    asm("mov.b64 %0, {%1, %1};" : "=l"(r) : "f"(x));
    return r;
}
__device__ __forceinline__ float2 unpack2(unsigned long long v) {
    float2 f;
    asm("mov.b64 {%0, %1}, %2;" : "=f"(f.x), "=f"(f.y) : "l"(v));
    return f;
}

// ---------------- prologue kernels ----------------

__global__ void zero_cnt_off_kernel(int n) {
    int i = blockIdx.x * blockDim.x + threadIdx.x;
    if (i < n) { g_cnt[i] = 0; g_off[i] = 0; }
}

// histogram of dst degree, 4 edges per thread (int4)
__global__ void hist_kernel(const int* __restrict__ ei, int nedges) {
    int t = blockIdx.x * blockDim.x + threadIdx.x;
    int e = t * 4;
    if (e + 4 <= nedges) {
        int4 d4 = *(const int4*)&ei[nedges + e];
        atomicAdd(&g_cnt[d4.x], 1);
        atomicAdd(&g_cnt[d4.y], 1);
        atomicAdd(&g_cnt[d4.z], 1);
        atomicAdd(&g_cnt[d4.w], 1);
    } else {
        for (int k = e; k < nedges; k++) atomicAdd(&g_cnt[ei[nedges + k]], 1);
    }
}

// phase 1: per-block (1024 elems) exclusive scan into rowptr, block sums to g_bsum
__global__ __launch_bounds__(1024) void scan1_kernel(int n) {
    __shared__ int warp_sums[32];
    int tid = threadIdx.x, lane = tid & 31, wid = tid >> 5;
    int i = blockIdx.x * 1024 + tid;
    int v = (i < n) ? g_cnt[i] : 0;
    int x = v;
    #pragma unroll
    for (int off = 1; off < 32; off <<= 1) {
        int t = __shfl_up_sync(0xffffffffu, x, off);
        if (lane >= off) x += t;
    }
    if (lane == 31) warp_sums[wid] = x;
    __syncthreads();
    if (wid == 0) {
        int ws = warp_sums[lane];
        #pragma unroll
        for (int off = 1; off < 32; off <<= 1) {
            int t = __shfl_up_sync(0xffffffffu, ws, off);
            if (lane >= off) ws += t;
        }
        warp_sums[lane] = ws;
    }
    __syncthreads();
    int woff = wid ? warp_sums[wid - 1] : 0;
    if (i < n) g_rowptr[i] = woff + x - v;       // block-local exclusive
    if (tid == 1023) g_bsum[blockIdx.x] = woff + x;
}

// phase 2: scan 98 block sums (single 128-thread block)
__global__ void scan2_kernel(int nb, int n) {
    __shared__ int ws[4];
    int tid = threadIdx.x, lane = tid & 31, wid = tid >> 5;
    int v = (tid < nb) ? g_bsum[tid] : 0;
    int x = v;
    #pragma unroll
    for (int off = 1; off < 32; off <<= 1) {
        int t = __shfl_up_sync(0xffffffffu, x, off);
        if (lane >= off) x += t;
    }
    if (lane == 31) ws[wid] = x;
    __syncthreads();
    int woff = 0;
    for (int w = 0; w < wid; w++) woff += ws[w];
    int excl = woff + x - v;
    if (tid < nb) g_boff[tid] = excl;
    if (tid == nb - 1) g_rowptr[n] = excl + v;
}

// phase 3: add block offsets + compute dinv (deg = in-deg + 1 self loop)
__global__ void scan3_dinv_kernel(int n) {
    int i = blockIdx.x * blockDim.x + threadIdx.x;
    if (i < n) {
        g_rowptr[i] += g_boff[i >> 10];
        g_dinv[i] = rsqrtf((float)(g_cnt[i] + 1));
    }
}

// fill CSR (by destination) with source indices, reading edge index directly
__global__ void fill_kernel(const int* __restrict__ ei, int nedges) {
    int e = blockIdx.x * blockDim.x + threadIdx.x;
    if (e >= nedges) return;
    int d = ei[nedges + e];
    int pos = g_rowptr[d] + atomicAdd(&g_off[d], 1);
    g_csr[pos] = ei[e];
}

// ---------------- GEMM: g_h(fp16) = dinv ⊙ (X(fp32) @ W) via fma.rn.f32x2 --------
// Tile 128 rows x 128 cols, KT=32 k-slab. 256 threads = 8 warps.
// Epilogue scales row by dinv[row] (folds per-source normalization into storage).
template <int LAYER>
__global__ __launch_bounds__(256) void gemm128_kernel(
    const float* __restrict__ Xin, const float* __restrict__ W, int nrows) {
    __shared__ unsigned long long XsS[128][32];  // 32 KB (splatted x)
    __shared__ float Ws[32][128];                // 16 KB
    const float* __restrict__ X = (LAYER == 1) ? Xin : (const float*)g_buf;

    const int tid  = threadIdx.x;
    const int lane = tid & 31;
    const int wid  = tid >> 5;
    const int row_blk = blockIdx.x * 128;
    const int row0 = wid * 16;

    unsigned long long acc[16][2];
    #pragma unroll
    for (int r = 0; r < 16; r++) { acc[r][0] = 0ull; acc[r][1] = 0ull; }

    for (int kt = 0; kt < 128; kt += 32) {
        const float4* Wg = (const float4*)&W[kt * 128];
        float4* Wsm = (float4*)&Ws[0][0];
        #pragma unroll
        for (int i = tid; i < 1024; i += 256) Wsm[i] = Wg[i];
        #pragma unroll
        for (int i = tid; i < 1024; i += 256) {
            int r = i >> 3;
            int j = i & 7;
            int gr = row_blk + r;
            float4 v = (gr < nrows) ? ((const float4*)&X[(size_t)gr * C + kt])[j]
                                    : make_float4(0.f, 0.f, 0.f, 0.f);
            XsS[r][4 * j + 0] = splat2(v.x);
            XsS[r][4 * j + 1] = splat2(v.y);
            XsS[r][4 * j + 2] = splat2(v.z);
            XsS[r][4 * j + 3] = splat2(v.w);
        }
        __syncthreads();
        #pragma unroll 4
        for (int k = 0; k < 32; k++) {
            ulonglong2 w = *(const ulonglong2*)&Ws[k][lane * 4];
            #pragma unroll
            for (int r = 0; r < 16; r++) {
                unsigned long long xv = XsS[row0 + r][k];
                acc[r][0] = fma2(xv, w.x, acc[r][0]);
                acc[r][1] = fma2(xv, w.y, acc[r][1]);
            }
        }
        __syncthreads();
    }
    #pragma unroll
    for (int r = 0; r < 16; r++) {
        int gr = row_blk + row0 + r;
        if (gr < nrows) {
            float di = g_dinv[gr];
            float2 a = unpack2(acc[r][0]);
            float2 b = unpack2(acc[r][1]);
            __half2 h01 = __floats2half2_rn(a.x * di, a.y * di);
            __half2 h23 = __floats2half2_rn(b.x * di, b.y * di);
            uint2 st;
            st.x = *(unsigned int*)&h01;
            st.y = *(unsigned int*)&h23;
            ((uint2*)&g_h[(size_t)gr * C])[lane] = st;
        }
    }
}

// ---------------- SpMM: warp-per-destination-row, weight-free gather ----------
// out[d] = dinv[d] * ( sum_{e in row d} h'[src_e] + h'[d] ) + bias
// h' already carries dinv[src]. LAYER=1: writes g_buf (+relu). LAYER=2: param out.
template <int LAYER>
__global__ __launch_bounds__(256) void spmm_kernel(
    const float* __restrict__ bias, float* __restrict__ outp, int n) {
    int warp = (blockIdx.x * blockDim.x + threadIdx.x) >> 5;
    int lane = threadIdx.x & 31;
    if (warp >= n) return;
    const uint2* __restrict__ H2 = (const uint2*)g_h;  // 8B/lane = 4 halves
    float* __restrict__ out = (LAYER == 1) ? (float*)g_buf : outp;
    float dd = g_dinv[warp];

    float4 acc;
    {
        uint2 raw = __ldcg(&H2[(size_t)warp * 32 + lane]);  // self loop: h'[d]
        float2 f0 = __half22float2(*(const __half2*)&raw.x);
        float2 f1 = __half22float2(*(const __half2*)&raw.y);
        acc = make_float4(f0.x, f0.y, f1.x, f1.y);
    }
    int e0 = g_rowptr[warp];
    int e1 = g_rowptr[warp + 1];
    int e = e0;
    // 8-way unrolled gather: no per-edge weight -> csr load feeds gather directly
    for (; e + 8 <= e1; e += 8) {
        uint2 r[8];
        #pragma unroll
        for (int j = 0; j < 8; j++) {
            int s = g_csr[e + j];
            r[j] = __ldcg(&H2[(size_t)s * 32 + lane]);
        }
        #pragma unroll
        for (int j = 0; j < 8; j++) {
            float2 f0 = __half22float2(*(const __half2*)&r[j].x);
            float2 f1 = __half22float2(*(const __half2*)&r[j].y);
            acc.x += f0.x; acc.y += f0.y; acc.z += f1.x; acc.w += f1.y;
        }
    }
    for (; e < e1; e++) {
        int s = g_csr[e];
        uint2 raw = __ldcg(&H2[(size_t)s * 32 + lane]);
        float2 f0 = __half22float2(*(const __half2*)&raw.x);
        float2 f1 = __half22float2(*(const __half2*)&raw.y);
        acc.x += f0.x; acc.y += f0.y; acc.z += f1.x; acc.w += f1.y;
    }
    float4 b = ((const float4*)bias)[lane];
    acc.x = acc.x * dd + b.x;
    acc.y = acc.y * dd + b.y;
    acc.z = acc.z * dd + b.z;
    acc.w = acc.w * dd + b.w;
    if (LAYER == 1) {
        acc.x = fmaxf(acc.x, 0.f);
        acc.y = fmaxf(acc.y, 0.f);
        acc.z = fmaxf(acc.z, 0.f);
        acc.w = fmaxf(acc.w, 0.f);
    }
    ((float4*)out)[(size_t)warp * 32 + lane] = acc;
}

// ---------------- launch ----------------
extern "C" void kernel_launch(void* const* d_in, const int* in_sizes, int n_in,
                              void* d_out, int out_size) {
    const float* x  = (const float*)d_in[0];
    const int*   ei = (const int*)d_in[1];     // int32 edge index (2 x E)
    const float* W1 = (const float*)d_in[2];
    const float* b1 = (const float*)d_in[3];
    const float* W2 = (const float*)d_in[4];
    const float* b2 = (const float*)d_in[5];
    float* out = (float*)d_out;

    const int nedges = in_sizes[1] / 2;   // 3,200,000
    const int n = NNODES;
    const int nb = (n + 1023) / 1024;     // 98 scan blocks

    zero_cnt_off_kernel<<<(n + 255) / 256, 256>>>(n);
    hist_kernel<<<(nedges / 4 + 255) / 256, 256>>>(ei, nedges);
    scan1_kernel<<<nb, 1024>>>(n);
    scan2_kernel<<<1, 128>>>(nb, n);
    scan3_dinv_kernel<<<(n + 255) / 256, 256>>>(n);
    fill_kernel<<<(nedges + 255) / 256, 256>>>(ei, nedges);

    const int gemm_blocks = (n + 127) / 128;      // 782
    const int spmm_blocks = (n * 32 + 255) / 256; // warp per row

    gemm128_kernel<1><<<gemm_blocks, 256>>>(x, W1, n);
    spmm_kernel<1><<<spmm_blocks, 256>>>(b1, nullptr, n);
    gemm128_kernel<2><<<gemm_blocks, 256>>>(nullptr, W2, n);
    spmm_kernel<2><<<spmm_blocks, 256>>>(b2, out, n);
}

// round 8
// speedup vs baseline: 2.0191x; 1.6644x over previous
#include <cuda_runtime.h>
#include <cuda_fp16.h>
#include <cstdint>

// Problem constants (fixed shapes)
#define NNODES 100000
#define NEDGES 3200000
#define C 128           // feature dim (in = hid = out = 128)

// ---------------- scratch (static device globals; no allocation) ----------------
__device__ __align__(16) int g_csr[NEDGES];
__device__ __align__(16) int g_rank[NEDGES];
__device__ int    g_cnt[NNODES];
__device__ int    g_rowptr[NNODES + 1];
__device__ int    g_bsum[128];
__device__ int    g_boff[128];
__device__ float  g_dinv[NNODES];
__device__ __align__(16) __half g_wt[C * C];               // W^T fp16 (n-major)
__device__ __align__(16) __half g_h[(size_t)NNODES * C];   // dinv-prescaled GEMM out, fp16
__device__ __align__(16) float  g_buf[(size_t)NNODES * C]; // layer-1 agg+relu output (fp32)

// dynamic shared memory for the tensor-core GEMM:
//   Xs  : 128 rows x 136 halves  (padded: 272B row stride -> conflict-free ldmatrix)
//   Wts : 128 rows x 136 halves
extern __shared__ __align__(16) __half g_smem[];
#define XS_STRIDE 136
#define WTS_OFF   (128 * XS_STRIDE)
#define GEMM_SMEM_BYTES (2 * 128 * XS_STRIDE * (int)sizeof(__half))

// ---------------- mma helpers ----------------
__device__ __forceinline__ unsigned sptr(const void* p) {
    return (unsigned)__cvta_generic_to_shared(p);
}
__device__ __forceinline__ void ldsm_x4(unsigned& r0, unsigned& r1,
                                        unsigned& r2, unsigned& r3, unsigned addr) {
    asm volatile("ldmatrix.sync.aligned.m8n8.x4.shared.b16 {%0,%1,%2,%3}, [%4];"
                 : "=r"(r0), "=r"(r1), "=r"(r2), "=r"(r3) : "r"(addr));
}
__device__ __forceinline__ void mma16816(float& d0, float& d1, float& d2, float& d3,
                                         unsigned a0, unsigned a1, unsigned a2, unsigned a3,
                                         unsigned b0, unsigned b1) {
    asm volatile(
        "mma.sync.aligned.m16n8k16.row.col.f32.f16.f16.f32 "
        "{%0,%1,%2,%3},{%4,%5,%6,%7},{%8,%9},{%0,%1,%2,%3};"
        : "+f"(d0), "+f"(d1), "+f"(d2), "+f"(d3)
        : "r"(a0), "r"(a1), "r"(a2), "r"(a3), "r"(b0), "r"(b1));
}

// ---------------- prologue kernels ----------------

__global__ void zero_cnt_kernel(int n) {
    int i = blockIdx.x * blockDim.x + threadIdx.x;
    if (i < n) g_cnt[i] = 0;
}

// histogram of dst degree + per-edge rank (4 edges per thread)
__global__ void hist_kernel(const int* __restrict__ ei, int nedges) {
    int t = blockIdx.x * blockDim.x + threadIdx.x;
    int e = t * 4;
    if (e + 4 <= nedges) {
        int4 d4 = *(const int4*)&ei[nedges + e];
        int4 r4;
        r4.x = atomicAdd(&g_cnt[d4.x], 1);
        r4.y = atomicAdd(&g_cnt[d4.y], 1);
        r4.z = atomicAdd(&g_cnt[d4.z], 1);
        r4.w = atomicAdd(&g_cnt[d4.w], 1);
        *(int4*)&g_rank[e] = r4;
    } else {
        for (int k = e; k < nedges; k++)
            g_rank[k] = atomicAdd(&g_cnt[ei[nedges + k]], 1);
    }
}

// phase 1: per-block (1024 elems) exclusive scan into rowptr, block sums to g_bsum
__global__ __launch_bounds__(1024) void scan1_kernel(int n) {
    __shared__ int warp_sums[32];
    int tid = threadIdx.x, lane = tid & 31, wid = tid >> 5;
    int i = blockIdx.x * 1024 + tid;
    int v = (i < n) ? g_cnt[i] : 0;
    int x = v;
    #pragma unroll
    for (int off = 1; off < 32; off <<= 1) {
        int t = __shfl_up_sync(0xffffffffu, x, off);
        if (lane >= off) x += t;
    }
    if (lane == 31) warp_sums[wid] = x;
    __syncthreads();
    if (wid == 0) {
        int ws = warp_sums[lane];
        #pragma unroll
        for (int off = 1; off < 32; off <<= 1) {
            int t = __shfl_up_sync(0xffffffffu, ws, off);
            if (lane >= off) ws += t;
        }
        warp_sums[lane] = ws;
    }
    __syncthreads();
    int woff = wid ? warp_sums[wid - 1] : 0;
    if (i < n) g_rowptr[i] = woff + x - v;
    if (tid == 1023) g_bsum[blockIdx.x] = woff + x;
}

// phase 2: scan 98 block sums
__global__ void scan2_kernel(int nb, int n) {
    __shared__ int ws[4];
    int tid = threadIdx.x, lane = tid & 31, wid = tid >> 5;
    int v = (tid < nb) ? g_bsum[tid] : 0;
    int x = v;
    #pragma unroll
    for (int off = 1; off < 32; off <<= 1) {
        int t = __shfl_up_sync(0xffffffffu, x, off);
        if (lane >= off) x += t;
    }
    if (lane == 31) ws[wid] = x;
    __syncthreads();
    int woff = 0;
    for (int w = 0; w < wid; w++) woff += ws[w];
    int excl = woff + x - v;
    if (tid < nb) g_boff[tid] = excl;
    if (tid == nb - 1) g_rowptr[n] = excl + v;
}

// phase 3: add block offsets + dinv (deg = in-deg + 1 self loop)
__global__ void scan3_dinv_kernel(int n) {
    int i = blockIdx.x * blockDim.x + threadIdx.x;
    if (i < n) {
        g_rowptr[i] += g_boff[i >> 10];
        g_dinv[i] = rsqrtf((float)(g_cnt[i] + 1));
    }
}

// fill CSR atomic-free using precomputed ranks (4 edges per thread)
__global__ void fill_kernel(const int* __restrict__ ei, int nedges) {
    int t = blockIdx.x * blockDim.x + threadIdx.x;
    int e = t * 4;
    if (e + 4 <= nedges) {
        int4 s4 = *(const int4*)&ei[e];
        int4 d4 = *(const int4*)&ei[nedges + e];
        int4 r4 = *(const int4*)&g_rank[e];
        g_csr[g_rowptr[d4.x] + r4.x] = s4.x;
        g_csr[g_rowptr[d4.y] + r4.y] = s4.y;
        g_csr[g_rowptr[d4.z] + r4.z] = s4.z;
        g_csr[g_rowptr[d4.w] + r4.w] = s4.w;
    } else {
        for (int k = e; k < nedges; k++)
            g_csr[g_rowptr[ei[nedges + k]] + g_rank[k]] = ei[k];
    }
}

// W (fp32 [k][n]) -> g_wt (fp16 [n][k])
__global__ void wt_kernel(const float* __restrict__ W) {
    int i = blockIdx.x * blockDim.x + threadIdx.x;   // 16384 threads
    int k = i >> 7, n = i & 127;                     // coalesced read
    g_wt[n * C + k] = __float2half(W[k * C + n]);
}

// ---------------- GEMM (tensor core): g_h(fp16) = dinv ⊙ (X @ W) --------------
// Block: 128 rows x 128 cols, K=128 resident. 8 warps: 4 (m) x 2 (n).
template <int LAYER>
__global__ __launch_bounds__(256) void gemm_tc_kernel(
    const float* __restrict__ Xin, int nrows) {
    __half* Xs  = g_smem;            // [128][136]
    __half* Wts = g_smem + WTS_OFF;  // [128][136]
    const float* __restrict__ X = (LAYER == 1) ? Xin : (const float*)g_buf;

    const int tid  = threadIdx.x;
    const int lane = tid & 31;
    const int wid  = tid >> 5;
    const int row_blk = blockIdx.x * 128;

    // load W^T (fp16, 128x128 halves = 2048 uint4)
    #pragma unroll
    for (int i = tid; i < 2048; i += 256) {
        int r = i >> 4, j = i & 15;
        *(uint4*)&Wts[r * XS_STRIDE + j * 8] = ((const uint4*)g_wt)[i];
    }
    // load X rows, convert fp32 -> fp16 (128 rows x 32 float4)
    #pragma unroll
    for (int i = tid; i < 4096; i += 256) {
        int r = i >> 5, j = i & 31;
        int gr = row_blk + r;
        float4 v = (gr < nrows) ? ((const float4*)&X[(size_t)gr * C])[j]
                                : make_float4(0.f, 0.f, 0.f, 0.f);
        __half2 h0 = __floats2half2_rn(v.x, v.y);
        __half2 h1 = __floats2half2_rn(v.z, v.w);
        uint2 st;
        st.x = *(unsigned*)&h0;
        st.y = *(unsigned*)&h1;
        *(uint2*)&Xs[r * XS_STRIDE + j * 4] = st;
    }
    __syncthreads();

    const int warp_m = wid & 3;        // 4 m-warps -> 32 rows each
    const int warp_n = wid >> 2;       // 2 n-warps -> 64 cols each
    const int m0 = warp_m * 32;
    const int n0 = warp_n * 64;

    float acc[2][8][4];
    #pragma unroll
    for (int mt = 0; mt < 2; mt++)
        #pragma unroll
        for (int nt = 0; nt < 8; nt++)
            #pragma unroll
            for (int q = 0; q < 4; q++) acc[mt][nt][q] = 0.f;

    #pragma unroll
    for (int ks = 0; ks < 8; ks++) {
        const int k0 = ks * 16;
        // A fragments: 16x16 each, lanes 0-15 rows @k0, lanes 16-31 rows @k0+8
        unsigned A0[4], A1[4];
        {
            const __half* p0 = &Xs[(m0 + 0 + (lane & 15)) * XS_STRIDE + k0 + (lane >> 4) * 8];
            ldsm_x4(A0[0], A0[1], A0[2], A0[3], sptr(p0));
            const __half* p1 = &Xs[(m0 + 16 + (lane & 15)) * XS_STRIDE + k0 + (lane >> 4) * 8];
            ldsm_x4(A1[0], A1[1], A1[2], A1[3], sptr(p1));
        }
        // B fragments: Wts is [n][k] row-major == mma ".col" B -> NON-trans ldmatrix.
        // lane group g=lane>>3: row = n0 + np*16 + (g>>1)*8 + (lane&7), col = k0 + (g&1)*8
        // -> tmp = {tile0.b0, tile0.b1, tile1.b0, tile1.b1}
        unsigned Bf[8][2];
        #pragma unroll
        for (int np = 0; np < 4; np++) {
            int g = lane >> 3;
            const __half* p = &Wts[(n0 + np * 16 + (g >> 1) * 8 + (lane & 7)) * XS_STRIDE
                                   + k0 + (g & 1) * 8];
            unsigned t0, t1, t2, t3;
            ldsm_x4(t0, t1, t2, t3, sptr(p));
            Bf[2 * np + 0][0] = t0; Bf[2 * np + 0][1] = t1;
            Bf[2 * np + 1][0] = t2; Bf[2 * np + 1][1] = t3;
        }
        #pragma unroll
        for (int nt = 0; nt < 8; nt++) {
            mma16816(acc[0][nt][0], acc[0][nt][1], acc[0][nt][2], acc[0][nt][3],
                     A0[0], A0[1], A0[2], A0[3], Bf[nt][0], Bf[nt][1]);
            mma16816(acc[1][nt][0], acc[1][nt][1], acc[1][nt][2], acc[1][nt][3],
                     A1[0], A1[1], A1[2], A1[3], Bf[nt][0], Bf[nt][1]);
        }
    }

    // epilogue: D fragment row = groupID(lane>>2) (+8), col = nt*8 + (lane&3)*2
    #pragma unroll
    for (int mt = 0; mt < 2; mt++) {
        int r0 = row_blk + m0 + mt * 16 + (lane >> 2);
        int r1 = r0 + 8;
        float di0 = (r0 < nrows) ? g_dinv[r0] : 0.f;
        float di1 = (r1 < nrows) ? g_dinv[r1] : 0.f;
        #pragma unroll
        for (int nt = 0; nt < 8; nt++) {
            int col = n0 + nt * 8 + (lane & 3) * 2;
            if (r0 < nrows) {
                __half2 h = __floats2half2_rn(acc[mt][nt][0] * di0, acc[mt][nt][1] * di0);
                *(unsigned*)&g_h[(size_t)r0 * C + col] = *(unsigned*)&h;
            }
            if (r1 < nrows) {
                __half2 h = __floats2half2_rn(acc[mt][nt][2] * di1, acc[mt][nt][3] * di1);
                *(unsigned*)&g_h[(size_t)r1 * C + col] = *(unsigned*)&h;
            }
        }
    }
}

// ---------------- SpMM: warp-per-destination-row, weight-free gather ----------
// out[d] = dinv[d] * ( sum_{e in row d} h'[src_e] + h'[d] ) + bias
template <int LAYER>
__global__ __launch_bounds__(256) void spmm_kernel(
    const float* __restrict__ bias, float* __restrict__ outp, int n) {
    int warp = (blockIdx.x * blockDim.x + threadIdx.x) >> 5;
    int lane = threadIdx.x & 31;
    if (warp >= n) return;
    const uint2* __restrict__ H2 = (const uint2*)g_h;
    float* __restrict__ out = (LAYER == 1) ? (float*)g_buf : outp;
    float dd = g_dinv[warp];

    float4 acc;
    {
        uint2 raw = __ldcg(&H2[(size_t)warp * 32 + lane]);  // self loop
        float2 f0 = __half22float2(*(const __half2*)&raw.x);
        float2 f1 = __half22float2(*(const __half2*)&raw.y);
        acc = make_float4(f0.x, f0.y, f1.x, f1.y);
    }
    int e0 = g_rowptr[warp];
    int e1 = g_rowptr[warp + 1];
    int e = e0;
    for (; e + 8 <= e1; e += 8) {
        uint2 r[8];
        #pragma unroll
        for (int j = 0; j < 8; j++) {
            int s = g_csr[e + j];
            r[j] = __ldcg(&H2[(size_t)s * 32 + lane]);
        }
        #pragma unroll
        for (int j = 0; j < 8; j++) {
            float2 f0 = __half22float2(*(const __half2*)&r[j].x);
            float2 f1 = __half22float2(*(const __half2*)&r[j].y);
            acc.x += f0.x; acc.y += f0.y; acc.z += f1.x; acc.w += f1.y;
        }
    }
    for (; e < e1; e++) {
        int s = g_csr[e];
        uint2 raw = __ldcg(&H2[(size_t)s * 32 + lane]);
        float2 f0 = __half22float2(*(const __half2*)&raw.x);
        float2 f1 = __half22float2(*(const __half2*)&raw.y);
        acc.x += f0.x; acc.y += f0.y; acc.z += f1.x; acc.w += f1.y;
    }
    float4 b = ((const float4*)bias)[lane];
    acc.x = acc.x * dd + b.x;
    acc.y = acc.y * dd + b.y;
    acc.z = acc.z * dd + b.z;
    acc.w = acc.w * dd + b.w;
    if (LAYER == 1) {
        acc.x = fmaxf(acc.x, 0.f);
        acc.y = fmaxf(acc.y, 0.f);
        acc.z = fmaxf(acc.z, 0.f);
        acc.w = fmaxf(acc.w, 0.f);
    }
    ((float4*)out)[(size_t)warp * 32 + lane] = acc;
}

// ---------------- launch ----------------
extern "C" void kernel_launch(void* const* d_in, const int* in_sizes, int n_in,
                              void* d_out, int out_size) {
    const float* x  = (const float*)d_in[0];
    const int*   ei = (const int*)d_in[1];     // int32 edge index (2 x E)
    const float* W1 = (const float*)d_in[2];
    const float* b1 = (const float*)d_in[3];
    const float* W2 = (const float*)d_in[4];
    const float* b2 = (const float*)d_in[5];
    float* out = (float*)d_out;

    const int nedges = in_sizes[1] / 2;   // 3,200,000
    const int n = NNODES;
    const int nb = (n + 1023) / 1024;     // 98 scan blocks

    cudaFuncSetAttribute(gemm_tc_kernel<1>,
                         cudaFuncAttributeMaxDynamicSharedMemorySize, GEMM_SMEM_BYTES);
    cudaFuncSetAttribute(gemm_tc_kernel<2>,
                         cudaFuncAttributeMaxDynamicSharedMemorySize, GEMM_SMEM_BYTES);

    zero_cnt_kernel<<<(n + 255) / 256, 256>>>(n);
    hist_kernel<<<(nedges / 4 + 255) / 256, 256>>>(ei, nedges);
    scan1_kernel<<<nb, 1024>>>(n);
    scan2_kernel<<<1, 128>>>(nb, n);
    scan3_dinv_kernel<<<(n + 255) / 256, 256>>>(n);
    fill_kernel<<<(nedges / 4 + 255) / 256, 256>>>(ei, nedges);

    const int gemm_blocks = (n + 127) / 128;      // 782
    const int spmm_blocks = (n * 32 + 255) / 256; // warp per row

    wt_kernel<<<64, 256>>>(W1);
    gemm_tc_kernel<1><<<gemm_blocks, 256, GEMM_SMEM_BYTES>>>(x, n);
    spmm_kernel<1><<<spmm_blocks, 256>>>(b1, nullptr, n);
    wt_kernel<<<64, 256>>>(W2);
    gemm_tc_kernel<2><<<gemm_blocks, 256, GEMM_SMEM_BYTES>>>(nullptr, n);
    spmm_kernel<2><<<spmm_blocks, 256>>>(b2, out, n);
}